// round 4
// baseline (speedup 1.0000x reference)
#include <cuda_runtime.h>
#include <cuda_bf16.h>
#include <cstdint>

// Problem constants (B=4, S=2048, D=1024, E=8, F=2048, top_k=2)
#define T_TOK 8192
#define D_DIM 1024
#define E_NUM 8
#define F_DIM 2048
#define RMAX  (2 * T_TOK)

#define BM 128
#define BN 128
#define BK 64                       // 64 int8 k-values per chunk (64B rows)
#define SMEM_SZ (1024 + 2 * 32768)  // tok/xq + 2 x (Ah|Al|Bh|Bl, 8KB each)

// ---------------- device scratch (no allocation allowed) --------------------
__device__ float   g_H[(size_t)RMAX * F_DIM];                   // fp32 H, 134MB
__device__ int8_t  g_w1q_hi[(size_t)E_NUM * F_DIM * D_DIM];     // [E][F][D]
__device__ int8_t  g_w1q_lo[(size_t)E_NUM * F_DIM * D_DIM];
__device__ int8_t  g_w2q_hi[(size_t)E_NUM * D_DIM * F_DIM];     // [E][D][F]
__device__ int8_t  g_w2q_lo[(size_t)E_NUM * D_DIM * F_DIM];
__device__ float   g_w1dq[E_NUM * F_DIM];
__device__ float   g_w2dq[E_NUM * D_DIM];
__device__ float   g_w1max[E_NUM * F_DIM];
__device__ float   g_w2max[E_NUM * D_DIM];
__device__ float   g_xq[T_TOK], g_xdq[T_TOK];
__device__ unsigned g_hmax[RMAX];
__device__ int   g_rows_token[RMAX];
__device__ float g_rows_w[RMAX];
__device__ int   g_top_i[2 * T_TOK];
__device__ float g_top_w[2 * T_TOK];
__device__ int   g_counts[E_NUM];
__device__ int   g_offsets[E_NUM];
__device__ int   g_cursor[E_NUM];

// ---------------- helpers ----------------------------------------------------
__device__ __forceinline__ uint32_t smem_u32(const void* p) {
    uint32_t a;
    asm("{ .reg .u64 t; cvta.to.shared.u64 t, %1; cvt.u32.u64 %0, t; }"
        : "=r"(a) : "l"(p));
    return a;
}
// 64B-row swizzle, conflict-free over 8-row ldmatrix groups:
// 16B-chunk col (bits 5:4) ^= (row&3) ^ (row>>2 & 1)
#define SWZ8(o) ((o) ^ (((((o) >> 6) & 3) ^ (((o) >> 8) & 1)) << 4))

__device__ __forceinline__ void ldsm4(uint32_t* r, uint32_t addr) {
    asm volatile("ldmatrix.sync.aligned.m8n8.x4.shared.b16 {%0,%1,%2,%3}, [%4];"
                 : "=r"(r[0]), "=r"(r[1]), "=r"(r[2]), "=r"(r[3]) : "r"(addr));
}
__device__ __forceinline__ void imma(int* c, const uint32_t* a, const uint32_t* b) {
    asm volatile(
        "mma.sync.aligned.m16n8k32.row.col.s32.s8.s8.s32 "
        "{%0,%1,%2,%3}, {%4,%5,%6,%7}, {%8,%9}, {%0,%1,%2,%3};"
        : "+r"(c[0]), "+r"(c[1]), "+r"(c[2]), "+r"(c[3])
        : "r"(a[0]), "r"(a[1]), "r"(a[2]), "r"(a[3]), "r"(b[0]), "r"(b[1]));
}

// quantize 32 fp32 -> 32 int8 hi + 32 int8 lo (2-limb, base 252)
__device__ __forceinline__ void quant32(const float* vv, float q,
                                        uint32_t* h8, uint32_t* l8) {
#pragma unroll
    for (int g4 = 0; g4 < 8; g4++) {
        uint32_t h = 0, l = 0;
#pragma unroll
        for (int j = 0; j < 4; j++) {
            float s  = vv[g4 * 4 + j] * q;
            int   hi = __float2int_rn(s);
            float r  = s - (float)hi;
            int   lo = __float2int_rn(r * 252.f);
            h |= (uint32_t)(hi & 255) << (8 * j);
            l |= (uint32_t)(lo & 255) << (8 * j);
        }
        h8[g4] = h;
        l8[g4] = l;
    }
}

// ---------------- init / router / scatter ------------------------------------
__global__ void init_kernel() {
    int i = threadIdx.x;
    if (i < E_NUM) { g_counts[i] = 0; g_cursor[i] = 0; }
}

__global__ void router_kernel(const float* __restrict__ x,
                              const int* __restrict__ mask,
                              const float* __restrict__ rw) {
    __shared__ float rws[E_NUM * D_DIM];
    for (int i = threadIdx.x; i < E_NUM * D_DIM; i += blockDim.x) {
        int d = i >> 3, e = i & 7;
        rws[e * D_DIM + d] = rw[i];
    }
    __syncthreads();

    int wid  = blockIdx.x * (blockDim.x >> 5) + (threadIdx.x >> 5);
    int lane = threadIdx.x & 31;
    if (wid >= T_TOK) return;

    const float* xp = x + (size_t)wid * D_DIM;
    float xr[32];
    float mx = 0.f;
#pragma unroll
    for (int j = 0; j < 32; j++) {
        xr[j] = xp[lane + 32 * j];
        mx = fmaxf(mx, fabsf(xr[j]));
    }
#pragma unroll
    for (int o = 16; o; o >>= 1) mx = fmaxf(mx, __shfl_xor_sync(0xffffffffu, mx, o));

    float lg[E_NUM];
#pragma unroll
    for (int e = 0; e < E_NUM; e++) {
        float acc = 0.f;
#pragma unroll
        for (int j = 0; j < 32; j++)
            acc = fmaf(xr[j], rws[e * D_DIM + lane + 32 * j], acc);
#pragma unroll
        for (int o = 16; o; o >>= 1) acc += __shfl_xor_sync(0xffffffffu, acc, o);
        lg[e] = acc;
    }

    if (lane == 0) {
        int i0 = 0; float v0 = lg[0];
#pragma unroll
        for (int e = 1; e < E_NUM; e++) if (lg[e] > v0) { v0 = lg[e]; i0 = e; }
        int i1 = -1; float v1 = -3.0e38f;
#pragma unroll
        for (int e = 0; e < E_NUM; e++)
            if (e != i0 && lg[e] > v1) { v1 = lg[e]; i1 = e; }
        float r = expf(v1 - v0);
        float s = 1.f + r;
        g_top_i[2 * wid] = i0;  g_top_i[2 * wid + 1] = i1;
        g_top_w[2 * wid] = 1.f / s;  g_top_w[2 * wid + 1] = r / s;
        float mxс = fmaxf(mx, 1e-30f);
        g_xq[wid]  = 126.5f / mxс;
        g_xdq[wid] = mxс * (1.f / 126.5f);
        if (mask[wid] != 0) {
            atomicAdd(&g_counts[i0], 1);
            atomicAdd(&g_counts[i1], 1);
        }
    }
}

__global__ void offsets_kernel() {
    if (threadIdx.x == 0) {
        int s = 0;
        for (int e = 0; e < E_NUM; e++) { g_offsets[e] = s; s += g_counts[e]; }
    }
}

__global__ void scatter_kernel(const int* __restrict__ mask) {
    int t = blockIdx.x * blockDim.x + threadIdx.x;
    if (t >= T_TOK) return;
    g_hmax[t] = 0u;                  // zero H row-max scratch (covers RMAX)
    g_hmax[t + T_TOK] = 0u;
    if (mask[t] == 0) return;
#pragma unroll
    for (int k = 0; k < 2; k++) {
        int e   = g_top_i[2 * t + k];
        int pos = atomicAdd(&g_cursor[e], 1);
        int idx = g_offsets[e] + pos;
        g_rows_token[idx] = t;
        g_rows_w[idx]     = g_top_w[2 * t + k];
    }
}

// ---------------- weight max + transpose/quantize ---------------------------
// w layout [E][K][N]; per-(e,n) max over K
__global__ void wmax_kernel(const float* __restrict__ w, float* __restrict__ omax,
                            int K, int N) {
    int e = blockIdx.y;
    int n = blockIdx.x * blockDim.x + threadIdx.x;
    if (n >= N) return;
    const float* p = w + (size_t)e * K * N + n;
    float m = 0.f;
    for (int k = 0; k < K; k++) m = fmaxf(m, fabsf(p[(size_t)k * N]));
    omax[e * N + n] = m;
}

// [E][K][N] fp32 -> [E][N][K] int8 hi/lo + dq per (e,n)
__device__ __forceinline__ void tq_body(const float* __restrict__ in,
                                        int8_t* __restrict__ ohi,
                                        int8_t* __restrict__ olo,
                                        const float* __restrict__ wmax,
                                        float* __restrict__ odq,
                                        int K, int N) {
    __shared__ float t[32][33];
    int k0 = blockIdx.y * 32, n0 = blockIdx.x * 32;
    size_t eb = (size_t)blockIdx.z * K * N;
    const float* p = in + eb + (size_t)k0 * N + n0;
#pragma unroll
    for (int i = 0; i < 4; i++)
        t[threadIdx.y + 8 * i][threadIdx.x] =
            p[(size_t)(threadIdx.y + 8 * i) * N + threadIdx.x];
    __syncthreads();
#pragma unroll
    for (int i = 0; i < 4; i++) {
        int n = n0 + threadIdx.y + 8 * i;
        float mxс = fmaxf(wmax[blockIdx.z * N + n], 1e-30f);
        float q = 126.5f / mxс;
        float v = t[threadIdx.x][threadIdx.y + 8 * i];
        float s = v * q;
        int   hi = __float2int_rn(s);
        int   lo = __float2int_rn((s - (float)hi) * 252.f);
        size_t o = eb + (size_t)n * K + k0 + threadIdx.x;
        ohi[o] = (int8_t)hi;
        olo[o] = (int8_t)lo;
        if (k0 + (int)threadIdx.x == 0)
            odq[blockIdx.z * N + n] = mxс * (1.f / 126.5f);
    }
}
__global__ void convert_w1(const float* __restrict__ w) {
    tq_body(w, g_w1q_hi, g_w1q_lo, g_w1max, g_w1dq, D_DIM, F_DIM);
}
__global__ void convert_w2(const float* __restrict__ w) {
    tq_body(w, g_w2q_hi, g_w2q_lo, g_w2max, g_w2dq, F_DIM, D_DIM);
}

// ---------------- grouped GEMM via IMMA m16n8k32 (2-limb int8) ---------------
// G1: H[r,:]  = relu(x[tok(r),:] @ w1[e] + b1[e])      K=1024, N=2048
// G2: out[t,:] += w(r) * (H[r,:] @ w2[e] + b2[e])      K=2048, N=1024
template <bool G1>
__global__ __launch_bounds__(256, 1)
void gemm_kernel(const float* __restrict__ xsrc,
                 const float* __restrict__ bias,
                 float* __restrict__ outp) {
    constexpr int KTOT = G1 ? D_DIM : F_DIM;
    constexpr int NTOT = G1 ? F_DIM : D_DIM;
    constexpr int NCH  = KTOT / BK;

    extern __shared__ __align__(1024) char smem[];
    const uint32_t sb = smem_u32(smem);
    int*   tok_s = (int*)smem;                 // [0,512)
    float* xq_s  = (float*)(smem + 512);       // [512,1024)
    const int BUF0 = 1024;  // per buffer: Ah 0 | Al 8192 | Bh 16384 | Bl 24576

    int e    = blockIdx.z;
    int n_e  = g_counts[e];
    int row0 = blockIdx.y * BM;
    if (row0 >= n_e) return;
    int base = g_offsets[e];
    int n0   = blockIdx.x * BN;

    int tid = threadIdx.x, w = tid >> 5, lane = tid & 31;
    int wm = w >> 2, wn = w & 3;               // 2x4 warps, warp tile 64m x 32n

    if (G1 && tid < BM) {
        int r  = row0 + tid;
        int tk = (r < n_e) ? g_rows_token[base + r] : -1;
        tok_s[tid] = tk;
        xq_s[tid]  = (tk >= 0) ? g_xq[tk] : 0.f;
    }
    __syncthreads();

    const int8_t* Bhi;
    const int8_t* Blo;
    if constexpr (G1) {
        Bhi = g_w1q_hi + ((size_t)e * F_DIM + n0) * D_DIM;
        Blo = g_w1q_lo + ((size_t)e * F_DIM + n0) * D_DIM;
    } else {
        Bhi = g_w2q_hi + ((size_t)e * D_DIM + n0) * F_DIM;
        Blo = g_w2q_lo + ((size_t)e * D_DIM + n0) * F_DIM;
    }

    // load geometry: row = tid&127 (conflict-free STS), 32B seg = tid>>7
    int lrow = tid & 127, lseg = tid >> 7;

    float qA = 0.f;
    const float* aptr = nullptr;
    if constexpr (G1) {
        int tk = tok_s[lrow];
        if (tk >= 0) { aptr = xsrc + (size_t)tk * D_DIM; qA = xq_s[lrow]; }
    } else {
        int rr = row0 + lrow; if (rr >= n_e) rr = n_e - 1;
        aptr = g_H + (size_t)(base + rr) * F_DIM;
        qA = 126.5f / fmaxf(__uint_as_float(g_hmax[base + rr]), 1e-30f);
    }

    uint32_t aH[8], aL[8];
    uint4 bH[2], bL[2];

    auto load_g = [&](int c) {
        int k0 = c * BK + lseg * 32;
        if (aptr) {
            float vv[32];
            const float4* fp = (const float4*)(aptr + k0);
#pragma unroll
            for (int i = 0; i < 8; i++) {
                float4 f = fp[i];
                vv[4 * i] = f.x; vv[4 * i + 1] = f.y;
                vv[4 * i + 2] = f.z; vv[4 * i + 3] = f.w;
            }
            quant32(vv, qA, aH, aL);
        } else {
#pragma unroll
            for (int i = 0; i < 8; i++) { aH[i] = 0u; aL[i] = 0u; }
        }
        const int8_t* bp = Bhi + (size_t)lrow * KTOT + k0;
        bH[0] = *(const uint4*)bp;
        bH[1] = *(const uint4*)(bp + 16);
        bp = Blo + (size_t)lrow * KTOT + k0;
        bL[0] = *(const uint4*)bp;
        bL[1] = *(const uint4*)(bp + 16);
    };

    auto sts = [&](int b) {
        char* bp = smem + BUF0 + b * 32768;
        int o = lrow * 64 + lseg * 32;
        *(uint4*)(bp + SWZ8(o))              = *(uint4*)&aH[0];
        *(uint4*)(bp + SWZ8(o + 16))         = *(uint4*)&aH[4];
        *(uint4*)(bp + 8192  + SWZ8(o))      = *(uint4*)&aL[0];
        *(uint4*)(bp + 8192  + SWZ8(o + 16)) = *(uint4*)&aL[4];
        *(uint4*)(bp + 16384 + SWZ8(o))      = bH[0];
        *(uint4*)(bp + 16384 + SWZ8(o + 16)) = bH[1];
        *(uint4*)(bp + 24576 + SWZ8(o))      = bL[0];
        *(uint4*)(bp + 24576 + SWZ8(o + 16)) = bL[1];
    };

    int acc_h[4][4][4], acc_x[4][4][4];
#pragma unroll
    for (int i = 0; i < 4; i++)
#pragma unroll
        for (int j = 0; j < 4; j++)
#pragma unroll
            for (int q = 0; q < 4; q++) { acc_h[i][j][q] = 0; acc_x[i][j][q] = 0; }

    // ldmatrix lane-address components
    int aR = (lane & 7) + ((lane >> 3) & 1) * 8;   // A row within m16 group
    int aC = lane >> 4;                            // A 16B col (0/1)
    int bR = (lane & 7) + (lane >> 4) * 8;         // B n-row within nf pair
    int bC = (lane >> 3) & 1;                      // B 16B col (0/1)

    load_g(0);
    sts(0);
    __syncthreads();

    for (int c = 0; c < NCH; c++) {
        int b = c & 1;
        if (c + 1 < NCH) load_g(c + 1);

        uint32_t bufA = sb + BUF0 + b * 32768;
        uint32_t bufB = bufA + 16384;
#pragma unroll
        for (int ks = 0; ks < 2; ks++) {
            uint32_t fA[4][4], fB[4][2], fB2[4][2], tmp[4];
            // A hi fragments
#pragma unroll
            for (int mf = 0; mf < 4; mf++) {
                int off = (wm * 64 + mf * 16 + aR) * 64 + (ks * 2 + aC) * 16;
                ldsm4(fA[mf], bufA + SWZ8(off));
            }
            // B hi fragments (x4 covers 2 n-frags)
#pragma unroll
            for (int pp = 0; pp < 2; pp++) {
                int off = (wn * 32 + pp * 16 + bR) * 64 + (ks * 2 + bC) * 16;
                ldsm4(tmp, bufB + SWZ8(off));
                fB[pp * 2][0] = tmp[0]; fB[pp * 2][1] = tmp[1];
                fB[pp * 2 + 1][0] = tmp[2]; fB[pp * 2 + 1][1] = tmp[3];
            }
#pragma unroll
            for (int mf = 0; mf < 4; mf++)
#pragma unroll
                for (int nf = 0; nf < 4; nf++)
                    imma(acc_h[mf][nf], fA[mf], fB[nf]);       // hi*hi
            // B lo fragments
#pragma unroll
            for (int pp = 0; pp < 2; pp++) {
                int off = (wn * 32 + pp * 16 + bR) * 64 + (ks * 2 + bC) * 16;
                ldsm4(tmp, bufB + 8192 + SWZ8(off));
                fB2[pp * 2][0] = tmp[0]; fB2[pp * 2][1] = tmp[1];
                fB2[pp * 2 + 1][0] = tmp[2]; fB2[pp * 2 + 1][1] = tmp[3];
            }
#pragma unroll
            for (int mf = 0; mf < 4; mf++)
#pragma unroll
                for (int nf = 0; nf < 4; nf++)
                    imma(acc_x[mf][nf], fA[mf], fB2[nf]);      // hi*lo
            // A lo fragments (reuse fA)
#pragma unroll
            for (int mf = 0; mf < 4; mf++) {
                int off = (wm * 64 + mf * 16 + aR) * 64 + (ks * 2 + aC) * 16;
                ldsm4(fA[mf], bufA + 8192 + SWZ8(off));
            }
#pragma unroll
            for (int mf = 0; mf < 4; mf++)
#pragma unroll
                for (int nf = 0; nf < 4; nf++)
                    imma(acc_x[mf][nf], fA[mf], fB[nf]);       // lo*hi
        }
        if (c + 1 < NCH) sts((c + 1) & 1);
        __syncthreads();
    }

    // ---------------- epilogue ----------------
    int g = lane >> 2, t4 = lane & 3;
    const float* dqB = G1 ? g_w1dq : g_w2dq;
    float bia[4][2], dqc[4][2];
#pragma unroll
    for (int nf = 0; nf < 4; nf++) {
#pragma unroll
        for (int j = 0; j < 2; j++) {
            int col = n0 + wn * 32 + nf * 8 + t4 * 2 + j;
            bia[nf][j] = bias[(size_t)e * NTOT + col];
            dqc[nf][j] = dqB[e * NTOT + col];
        }
    }

#pragma unroll
    for (int mf = 0; mf < 4; mf++) {
#pragma unroll
        for (int half = 0; half < 2; half++) {
            int  r   = row0 + wm * 64 + mf * 16 + g + half * 8;
            bool val = (r < n_e);
            if constexpr (G1) {
                float dq_r = val ? g_xdq[tok_s[r - row0]] : 0.f;
                float m = 0.f;
                float2 vs[4];
#pragma unroll
                for (int nf = 0; nf < 4; nf++) {
                    float v0 = ((float)acc_h[mf][nf][2 * half + 0] +
                                (float)acc_x[mf][nf][2 * half + 0] * (1.f / 252.f)) *
                                   dq_r * dqc[nf][0] + bia[nf][0];
                    float v1 = ((float)acc_h[mf][nf][2 * half + 1] +
                                (float)acc_x[mf][nf][2 * half + 1] * (1.f / 252.f)) *
                                   dq_r * dqc[nf][1] + bia[nf][1];
                    v0 = fmaxf(v0, 0.f); v1 = fmaxf(v1, 0.f);
                    vs[nf] = make_float2(v0, v1);
                    m = fmaxf(m, fmaxf(v0, v1));
                }
                if (val) {
                    size_t ro = (size_t)(base + r) * F_DIM;
#pragma unroll
                    for (int nf = 0; nf < 4; nf++) {
                        int col = n0 + wn * 32 + nf * 8 + t4 * 2;
                        *(float2*)(g_H + ro + col) = vs[nf];
                    }
                } else {
                    m = 0.f;
                }
                m = fmaxf(m, __shfl_xor_sync(0xffffffffu, m, 1));
                m = fmaxf(m, __shfl_xor_sync(0xffffffffu, m, 2));
                if (val && t4 == 0)
                    atomicMax(&g_hmax[base + r], __float_as_uint(m));
            } else {
                if (val) {
                    int   t  = g_rows_token[base + r];
                    float ww = g_rows_w[base + r];
                    float dq_r = __uint_as_float(g_hmax[base + r]) * (1.f / 126.5f);
                    float* op = outp + (size_t)t * D_DIM;
#pragma unroll
                    for (int nf = 0; nf < 4; nf++) {
#pragma unroll
                        for (int j = 0; j < 2; j++) {
                            int col = n0 + wn * 32 + nf * 8 + t4 * 2 + j;
                            float v = ((float)acc_h[mf][nf][2 * half + j] +
                                       (float)acc_x[mf][nf][2 * half + j] * (1.f / 252.f)) *
                                          dq_r * dqc[nf][j] + bia[nf][j];
                            atomicAdd(op + col, ww * v);
                        }
                    }
                }
            }
        }
    }
}

// ---------------- launch -----------------------------------------------------
extern "C" void kernel_launch(void* const* d_in, const int* in_sizes, int n_in,
                              void* d_out, int out_size) {
    const float* x    = (const float*)d_in[0];
    const int*   mask = (const int*)d_in[1];
    const float* rw   = (const float*)d_in[2];
    const float* w1   = (const float*)d_in[3];
    const float* b1   = (const float*)d_in[4];
    const float* w2   = (const float*)d_in[5];
    const float* b2   = (const float*)d_in[6];
    float*       out  = (float*)d_out;

    cudaFuncSetAttribute(gemm_kernel<true>,
                         cudaFuncAttributeMaxDynamicSharedMemorySize, SMEM_SZ);
    cudaFuncSetAttribute(gemm_kernel<false>,
                         cudaFuncAttributeMaxDynamicSharedMemorySize, SMEM_SZ);

    cudaMemsetAsync(out, 0, (size_t)T_TOK * D_DIM * sizeof(float));
    init_kernel<<<1, 32>>>();

    float *w1max_p, *w2max_p;
    cudaGetSymbolAddress((void**)&w1max_p, g_w1max);
    cudaGetSymbolAddress((void**)&w2max_p, g_w2max);
    wmax_kernel<<<dim3(F_DIM / 256, E_NUM), 256>>>(w1, w1max_p, D_DIM, F_DIM);
    wmax_kernel<<<dim3(D_DIM / 256, E_NUM), 256>>>(w2, w2max_p, F_DIM, D_DIM);
    convert_w1<<<dim3(F_DIM / 32, D_DIM / 32, E_NUM), dim3(32, 8)>>>(w1);
    convert_w2<<<dim3(D_DIM / 32, F_DIM / 32, E_NUM), dim3(32, 8)>>>(w2);

    router_kernel<<<T_TOK / 8, 256>>>(x, mask, rw);
    offsets_kernel<<<1, 32>>>();
    scatter_kernel<<<(T_TOK + 255) / 256, 256>>>(mask);

    dim3 g1(F_DIM / BN, RMAX / BM, E_NUM);
    gemm_kernel<true><<<g1, 256, SMEM_SZ>>>(x, b1, out);
    dim3 g2(D_DIM / BN, RMAX / BM, E_NUM);
    gemm_kernel<false><<<g2, 256, SMEM_SZ>>>(x, b2, out);
}

// round 5
// speedup vs baseline: 3.9234x; 3.9234x over previous
#include <cuda_runtime.h>
#include <cuda_fp16.h>
#include <cstdint>

// Problem constants (B=4, S=2048, D=1024, E=8, F=2048, top_k=2)
#define T_TOK 8192
#define D_DIM 1024
#define E_NUM 8
#define F_DIM 2048
#define RMAX  (2 * T_TOK)

#define BM 128
#define BN 128
#define BK 64                         // 64 fp16 k-values = 128B rows
#define STAGE_BYTES (3 * 16384)       // Ah | Al | B, 16KB each
#define SMEM_SZ (1024 + 3 * STAGE_BYTES)

// ---------------- device scratch (no allocation allowed) --------------------
__device__ __half g_xh[(size_t)T_TOK * D_DIM];                 // x split hi
__device__ __half g_xl[(size_t)T_TOK * D_DIM];                 // x split lo
__device__ __half g_Hh[(size_t)RMAX * F_DIM];                  // H split hi
__device__ __half g_Hl[(size_t)RMAX * F_DIM];                  // H split lo
__device__ __half g_w1t[(size_t)E_NUM * F_DIM * D_DIM];        // [E][F][D] fp16
__device__ __half g_w2t[(size_t)E_NUM * D_DIM * F_DIM];        // [E][D][F] fp16
__device__ int   g_rows_token[RMAX];
__device__ float g_rows_w[RMAX];
__device__ int   g_top_i[2 * T_TOK];
__device__ float g_top_w[2 * T_TOK];
__device__ int   g_counts[E_NUM];
__device__ int   g_offsets[E_NUM];
__device__ int   g_cursor[E_NUM];

// ---------------- helpers ----------------------------------------------------
__device__ __forceinline__ uint32_t smem_u32(const void* p) {
    uint32_t a;
    asm("{ .reg .u64 t; cvta.to.shared.u64 t, %1; cvt.u32.u64 %0, t; }"
        : "=r"(a) : "l"(p));
    return a;
}
// standard 128B-row swizzle (Swizzle<3,4,3>): 16B-col bits[6:4] ^= row bits[9:7]
#define SWZ128(o) ((o) ^ (((o) >> 3) & 0x70))

__device__ __forceinline__ void ldsm4(uint32_t* r, uint32_t addr) {
    asm volatile("ldmatrix.sync.aligned.m8n8.x4.shared.b16 {%0,%1,%2,%3}, [%4];"
                 : "=r"(r[0]), "=r"(r[1]), "=r"(r[2]), "=r"(r[3]) : "r"(addr));
}
__device__ __forceinline__ void hmma(float* c, const uint32_t* a,
                                     const uint32_t* b) {
    asm volatile(
        "mma.sync.aligned.m16n8k16.row.col.f32.f16.f16.f32 "
        "{%0,%1,%2,%3}, {%4,%5,%6,%7}, {%8,%9}, {%0,%1,%2,%3};"
        : "+f"(c[0]), "+f"(c[1]), "+f"(c[2]), "+f"(c[3])
        : "r"(a[0]), "r"(a[1]), "r"(a[2]), "r"(a[3]), "r"(b[0]), "r"(b[1]));
}
__device__ __forceinline__ void cp16(uint32_t dst, const void* src, int nbytes) {
    asm volatile("cp.async.cg.shared.global [%0], [%1], 16, %2;"
                 :: "r"(dst), "l"(src), "r"(nbytes) : "memory");
}
__device__ __forceinline__ void cp_commit() {
    asm volatile("cp.async.commit_group;" ::: "memory");
}
__device__ __forceinline__ void cp_wait1() {
    asm volatile("cp.async.wait_group 1;" ::: "memory");
}

// ---------------- init / router / scatter ------------------------------------
__global__ void init_kernel() {
    int i = threadIdx.x;
    if (i < E_NUM) { g_counts[i] = 0; g_cursor[i] = 0; }
}

__global__ void router_kernel(const float* __restrict__ x,
                              const int* __restrict__ mask,
                              const float* __restrict__ rw) {
    __shared__ float rws[E_NUM * D_DIM];
    for (int i = threadIdx.x; i < E_NUM * D_DIM; i += blockDim.x) {
        int d = i >> 3, e = i & 7;
        rws[e * D_DIM + d] = rw[i];
    }
    __syncthreads();

    int wid  = blockIdx.x * (blockDim.x >> 5) + (threadIdx.x >> 5);
    int lane = threadIdx.x & 31;
    if (wid >= T_TOK) return;

    const float* xp = x + (size_t)wid * D_DIM;
    float xr[32];
#pragma unroll
    for (int j = 0; j < 32; j++) xr[j] = xp[lane + 32 * j];

    float lg[E_NUM];
#pragma unroll
    for (int e = 0; e < E_NUM; e++) {
        float acc = 0.f;
#pragma unroll
        for (int j = 0; j < 32; j++)
            acc = fmaf(xr[j], rws[e * D_DIM + lane + 32 * j], acc);
#pragma unroll
        for (int o = 16; o; o >>= 1) acc += __shfl_xor_sync(0xffffffffu, acc, o);
        lg[e] = acc;
    }

    if (lane == 0) {
        int i0 = 0; float v0 = lg[0];
#pragma unroll
        for (int e = 1; e < E_NUM; e++) if (lg[e] > v0) { v0 = lg[e]; i0 = e; }
        int i1 = -1; float v1 = -3.0e38f;
#pragma unroll
        for (int e = 0; e < E_NUM; e++)
            if (e != i0 && lg[e] > v1) { v1 = lg[e]; i1 = e; }
        float r = expf(v1 - v0);
        float s = 1.f + r;
        g_top_i[2 * wid] = i0;  g_top_i[2 * wid + 1] = i1;
        g_top_w[2 * wid] = 1.f / s;  g_top_w[2 * wid + 1] = r / s;
        if (mask[wid] != 0) {
            atomicAdd(&g_counts[i0], 1);
            atomicAdd(&g_counts[i1], 1);
        }
    }
}

__global__ void offsets_kernel() {
    if (threadIdx.x == 0) {
        int s = 0;
        for (int e = 0; e < E_NUM; e++) { g_offsets[e] = s; s += g_counts[e]; }
    }
}

__global__ void scatter_kernel(const int* __restrict__ mask) {
    int t = blockIdx.x * blockDim.x + threadIdx.x;
    if (t >= T_TOK || mask[t] == 0) return;
#pragma unroll
    for (int k = 0; k < 2; k++) {
        int e   = g_top_i[2 * t + k];
        int pos = atomicAdd(&g_cursor[e], 1);
        int idx = g_offsets[e] + pos;
        g_rows_token[idx] = t;
        g_rows_w[idx]     = g_top_w[2 * t + k];
    }
}

// ---------------- x split into fp16 hi/lo ------------------------------------
__global__ void convert_x(const float* __restrict__ x) {
    size_t i = ((size_t)blockIdx.x * blockDim.x + threadIdx.x) * 8;
    if (i >= (size_t)T_TOK * D_DIM) return;
    float4 a = *(const float4*)(x + i);
    float4 b = *(const float4*)(x + i + 4);
    float f[8] = {a.x, a.y, a.z, a.w, b.x, b.y, b.z, b.w};
    __half h[8], l[8];
#pragma unroll
    for (int j = 0; j < 8; j++) {
        h[j] = __float2half(f[j]);
        l[j] = __float2half(f[j] - __half2float(h[j]));
    }
    *(uint4*)(g_xh + i) = *(uint4*)h;
    *(uint4*)(g_xl + i) = *(uint4*)l;
}

// ---------------- weight transpose to fp16 -----------------------------------
// in: [E][K][N] fp32 -> out: [E][N][K] fp16
__device__ __forceinline__ void tq_body(const float* __restrict__ in,
                                        __half* __restrict__ o16,
                                        int K, int N) {
    __shared__ float t[32][33];
    int k0 = blockIdx.y * 32, n0 = blockIdx.x * 32;
    size_t eb = (size_t)blockIdx.z * K * N;
    const float* p = in + eb + (size_t)k0 * N + n0;
#pragma unroll
    for (int i = 0; i < 4; i++)
        t[threadIdx.y + 8 * i][threadIdx.x] =
            p[(size_t)(threadIdx.y + 8 * i) * N + threadIdx.x];
    __syncthreads();
#pragma unroll
    for (int i = 0; i < 4; i++) {
        int n = n0 + threadIdx.y + 8 * i;
        float v = t[threadIdx.x][threadIdx.y + 8 * i];
        o16[eb + (size_t)n * K + k0 + threadIdx.x] = __float2half(v);
    }
}
__global__ void convert_w1(const float* __restrict__ w) {
    tq_body(w, g_w1t, D_DIM, F_DIM);
}
__global__ void convert_w2(const float* __restrict__ w) {
    tq_body(w, g_w2t, F_DIM, D_DIM);
}

// ---------------- grouped GEMM: fp16 HMMA, A split hi/lo, B single -----------
// G1: H[r,:]  = relu(x[tok(r),:] @ w1[e] + b1[e])      K=1024, N=2048
// G2: out[t,:] += w(r) * (H[r,:] @ w2[e] + b2[e])      K=2048, N=1024
template <bool G1>
__global__ __launch_bounds__(256, 1)
void gemm_kernel(const float* __restrict__ bias, float* __restrict__ outp) {
    constexpr int KTOT = G1 ? D_DIM : F_DIM;
    constexpr int NTOT = G1 ? F_DIM : D_DIM;
    constexpr int NCH  = KTOT / BK;

    extern __shared__ __align__(1024) char smem[];
    const uint32_t sb = smem_u32(smem);
    int* tok_s = (int*)smem;                 // [0,512)
    const int BUF0 = 1024;                   // 3 stages x (Ah 16K | Al 16K | B 16K)

    int e    = blockIdx.z;
    int n_e  = g_counts[e];
    int row0 = blockIdx.y * BM;
    if (row0 >= n_e) return;
    int base = g_offsets[e];
    int n0   = blockIdx.x * BN;

    int tid = threadIdx.x, w = tid >> 5, lane = tid & 31;
    int wm = w >> 2, wn = w & 3;             // 2x4 warps, warp tile 64m x 32n

    if (G1 && tid < BM) {
        int r = row0 + tid;
        tok_s[tid] = (r < n_e) ? g_rows_token[base + r] : -1;
    }
    __syncthreads();

    const __half* Bw = G1 ? (g_w1t + ((size_t)e * F_DIM + n0) * D_DIM)
                          : (g_w2t + ((size_t)e * D_DIM + n0) * F_DIM);

    // load geometry: 2 threads per row; each thread 4x16B per matrix
    int lrow = tid >> 1, lhalf = tid & 1;

    const __half* aH;
    const __half* aL;
    int azf = 16;
    if constexpr (G1) {
        int tk = tok_s[lrow];
        if (tk >= 0) {
            aH = g_xh + (size_t)tk * D_DIM;
            aL = g_xl + (size_t)tk * D_DIM;
        } else {
            aH = g_xh; aL = g_xl; azf = 0;   // zero-fill
        }
    } else {
        int rr = row0 + lrow; if (rr >= n_e) rr = n_e - 1;
        aH = g_Hh + (size_t)(base + rr) * F_DIM;
        aL = g_Hl + (size_t)(base + rr) * F_DIM;
    }
    const __half* bR_ = Bw + (size_t)lrow * KTOT;

    auto issue = [&](int c) {
        int stage = c % 3;
        int k0 = c * BK;
        uint32_t dA = sb + BUF0 + stage * STAGE_BYTES;
        uint32_t dL = dA + 16384;
        uint32_t dB = dA + 32768;
#pragma unroll
        for (int s = 0; s < 4; s++) {
            int cb = (lhalf * 4 + s) * 16;               // byte within 128B row
            uint32_t doff = SWZ128(lrow * 128 + cb);
            const char* sa = (const char*)(aH + k0) + cb;
            const char* sl = (const char*)(aL + k0) + cb;
            const char* sbp = (const char*)(bR_ + k0) + cb;
            cp16(dA + doff, sa, azf);
            cp16(dL + doff, sl, azf);
            cp16(dB + doff, sbp, 16);
        }
        cp_commit();
    };

    float acc[4][4][4];
#pragma unroll
    for (int i = 0; i < 4; i++)
#pragma unroll
        for (int j = 0; j < 4; j++)
#pragma unroll
            for (int q = 0; q < 4; q++) acc[i][j][q] = 0.f;

    // ldmatrix lane-address components (validated R3/R4 geometry)
    int aR = (lane & 7) + ((lane >> 3) & 1) * 8;
    int aC = lane >> 4;
    int bRw = (lane & 7) + (lane >> 4) * 8;
    int bC = (lane >> 3) & 1;

    issue(0);
    issue(1);

    for (int c = 0; c < NCH; c++) {
        cp_wait1();
        __syncthreads();
        if (c + 2 < NCH) issue(c + 2);
        else cp_commit();                    // keep group accounting uniform

        uint32_t bufA = sb + BUF0 + (c % 3) * STAGE_BYTES;
        uint32_t bufL = bufA + 16384;
        uint32_t bufB = bufA + 32768;
#pragma unroll
        for (int ks = 0; ks < 4; ks++) {
            uint32_t fB[4][2], tmp[4];
#pragma unroll
            for (int pp = 0; pp < 2; pp++) {
                int off = (wn * 32 + pp * 16 + bRw) * 128 + (ks * 2 + bC) * 16;
                ldsm4(tmp, bufB + SWZ128(off));
                fB[pp * 2][0] = tmp[0]; fB[pp * 2][1] = tmp[1];
                fB[pp * 2 + 1][0] = tmp[2]; fB[pp * 2 + 1][1] = tmp[3];
            }
            uint32_t fAh[4][4], fAl[4][4];
#pragma unroll
            for (int mf = 0; mf < 4; mf++) {
                int off = (wm * 64 + mf * 16 + aR) * 128 + (ks * 2 + aC) * 16;
                ldsm4(fAh[mf], bufA + SWZ128(off));
                ldsm4(fAl[mf], bufL + SWZ128(off));
            }
#pragma unroll
            for (int mf = 0; mf < 4; mf++)
#pragma unroll
                for (int nf = 0; nf < 4; nf++) {
                    hmma(acc[mf][nf], fAh[mf], fB[nf]);   // hi * B
                    hmma(acc[mf][nf], fAl[mf], fB[nf]);   // lo * B (same acc)
                }
        }
        __syncthreads();
    }

    // ---------------- epilogue ----------------
    int g = lane >> 2, t4 = lane & 3;
    float bia[4][2];
#pragma unroll
    for (int nf = 0; nf < 4; nf++) {
#pragma unroll
        for (int j = 0; j < 2; j++)
            bia[nf][j] = bias[(size_t)e * NTOT + n0 + wn * 32 + nf * 8 + t4 * 2 + j];
    }

#pragma unroll
    for (int mf = 0; mf < 4; mf++) {
#pragma unroll
        for (int half = 0; half < 2; half++) {
            int r = row0 + wm * 64 + mf * 16 + g + half * 8;
            if (r >= n_e) continue;
            if constexpr (G1) {
                size_t ro = (size_t)(base + r) * F_DIM;
#pragma unroll
                for (int nf = 0; nf < 4; nf++) {
                    int col = n0 + wn * 32 + nf * 8 + t4 * 2;
                    float v0 = fmaxf(acc[mf][nf][2 * half + 0] + bia[nf][0], 0.f);
                    float v1 = fmaxf(acc[mf][nf][2 * half + 1] + bia[nf][1], 0.f);
                    __half h0 = __float2half(v0);
                    __half h1 = __float2half(v1);
                    __half l0 = __float2half(v0 - __half2float(h0));
                    __half l1 = __float2half(v1 - __half2float(h1));
                    *(__half2*)(g_Hh + ro + col) = __halves2half2(h0, h1);
                    *(__half2*)(g_Hl + ro + col) = __halves2half2(l0, l1);
                }
            } else {
                int   t  = g_rows_token[base + r];
                float ww = g_rows_w[base + r];
                float* op = outp + (size_t)t * D_DIM;
#pragma unroll
                for (int nf = 0; nf < 4; nf++) {
                    int col = n0 + wn * 32 + nf * 8 + t4 * 2;
                    atomicAdd(op + col,
                              ww * (acc[mf][nf][2 * half + 0] + bia[nf][0]));
                    atomicAdd(op + col + 1,
                              ww * (acc[mf][nf][2 * half + 1] + bia[nf][1]));
                }
            }
        }
    }
}

// ---------------- launch -----------------------------------------------------
extern "C" void kernel_launch(void* const* d_in, const int* in_sizes, int n_in,
                              void* d_out, int out_size) {
    const float* x    = (const float*)d_in[0];
    const int*   mask = (const int*)d_in[1];
    const float* rw   = (const float*)d_in[2];
    const float* w1   = (const float*)d_in[3];
    const float* b1   = (const float*)d_in[4];
    const float* w2   = (const float*)d_in[5];
    const float* b2   = (const float*)d_in[6];
    float*       out  = (float*)d_out;

    cudaFuncSetAttribute(gemm_kernel<true>,
                         cudaFuncAttributeMaxDynamicSharedMemorySize, SMEM_SZ);
    cudaFuncSetAttribute(gemm_kernel<false>,
                         cudaFuncAttributeMaxDynamicSharedMemorySize, SMEM_SZ);

    cudaMemsetAsync(out, 0, (size_t)T_TOK * D_DIM * sizeof(float));
    init_kernel<<<1, 32>>>();

    convert_x<<<(T_TOK * D_DIM / 8 + 255) / 256, 256>>>(x);
    convert_w1<<<dim3(F_DIM / 32, D_DIM / 32, E_NUM), dim3(32, 8)>>>(w1);
    convert_w2<<<dim3(D_DIM / 32, F_DIM / 32, E_NUM), dim3(32, 8)>>>(w2);

    router_kernel<<<T_TOK / 8, 256>>>(x, mask, rw);
    offsets_kernel<<<1, 32>>>();
    scatter_kernel<<<(T_TOK + 255) / 256, 256>>>(mask);

    dim3 g1(F_DIM / BN, RMAX / BM, E_NUM);
    gemm_kernel<true><<<g1, 256, SMEM_SZ>>>(b1, out);
    dim3 g2(D_DIM / BN, RMAX / BM, E_NUM);
    gemm_kernel<false><<<g2, 256, SMEM_SZ>>>(b2, out);
}

// round 6
// speedup vs baseline: 5.9620x; 1.5196x over previous
#include <cuda_runtime.h>
#include <cuda_fp16.h>
#include <cstdint>

// Problem constants (B=4, S=2048, D=1024, E=8, F=2048, top_k=2)
#define T_TOK 8192
#define D_DIM 1024
#define E_NUM 8
#define F_DIM 2048
#define RMAX  (2 * T_TOK)

#define BM 128
#define BN 128
#define BK 64                         // 64 fp16 k-values = 128B rows
#define STAGE_BYTES (2 * 16384)       // A | B, 16KB each
#define SMEM_SZ (1024 + 3 * STAGE_BYTES)

// ---------------- device scratch (no allocation allowed) --------------------
__device__ __half g_x16[(size_t)T_TOK * D_DIM];                // x fp16
__device__ __half g_H16[(size_t)RMAX * F_DIM];                 // H fp16
__device__ __half g_w1t[(size_t)E_NUM * F_DIM * D_DIM];        // [E][F][D] fp16
__device__ __half g_w2t[(size_t)E_NUM * D_DIM * F_DIM];        // [E][D][F] fp16
__device__ int   g_rows_token[RMAX];
__device__ float g_rows_w[RMAX];
__device__ int   g_top_i[2 * T_TOK];
__device__ float g_top_w[2 * T_TOK];
__device__ int   g_counts[E_NUM];
__device__ int   g_offsets[E_NUM];
__device__ int   g_cursor[E_NUM];

// ---------------- helpers ----------------------------------------------------
__device__ __forceinline__ uint32_t smem_u32(const void* p) {
    uint32_t a;
    asm("{ .reg .u64 t; cvta.to.shared.u64 t, %1; cvt.u32.u64 %0, t; }"
        : "=r"(a) : "l"(p));
    return a;
}
// standard 128B-row swizzle (Swizzle<3,4,3>): 16B-col bits[6:4] ^= row bits[9:7]
#define SWZ128(o) ((o) ^ (((o) >> 3) & 0x70))

__device__ __forceinline__ void ldsm4(uint32_t* r, uint32_t addr) {
    asm volatile("ldmatrix.sync.aligned.m8n8.x4.shared.b16 {%0,%1,%2,%3}, [%4];"
                 : "=r"(r[0]), "=r"(r[1]), "=r"(r[2]), "=r"(r[3]) : "r"(addr));
}
__device__ __forceinline__ void hmma(float* c, const uint32_t* a,
                                     const uint32_t* b) {
    asm volatile(
        "mma.sync.aligned.m16n8k16.row.col.f32.f16.f16.f32 "
        "{%0,%1,%2,%3}, {%4,%5,%6,%7}, {%8,%9}, {%0,%1,%2,%3};"
        : "+f"(c[0]), "+f"(c[1]), "+f"(c[2]), "+f"(c[3])
        : "r"(a[0]), "r"(a[1]), "r"(a[2]), "r"(a[3]), "r"(b[0]), "r"(b[1]));
}
__device__ __forceinline__ void cp16(uint32_t dst, const void* src, int nbytes) {
    asm volatile("cp.async.cg.shared.global [%0], [%1], 16, %2;"
                 :: "r"(dst), "l"(src), "r"(nbytes) : "memory");
}
__device__ __forceinline__ void cp_commit() {
    asm volatile("cp.async.commit_group;" ::: "memory");
}
__device__ __forceinline__ void cp_wait1() {
    asm volatile("cp.async.wait_group 1;" ::: "memory");
}

// ---------------- init / router / scatter ------------------------------------
__global__ void init_kernel() {
    int i = threadIdx.x;
    if (i < E_NUM) { g_counts[i] = 0; g_cursor[i] = 0; }
}

__global__ void router_kernel(const float* __restrict__ x,
                              const int* __restrict__ mask,
                              const float* __restrict__ rw) {
    __shared__ float rws[E_NUM * D_DIM];
    for (int i = threadIdx.x; i < E_NUM * D_DIM; i += blockDim.x) {
        int d = i >> 3, e = i & 7;
        rws[e * D_DIM + d] = rw[i];
    }
    __syncthreads();

    int wid  = blockIdx.x * (blockDim.x >> 5) + (threadIdx.x >> 5);
    int lane = threadIdx.x & 31;
    if (wid >= T_TOK) return;

    const float* xp = x + (size_t)wid * D_DIM;
    float xr[32];
#pragma unroll
    for (int j = 0; j < 32; j++) xr[j] = xp[lane + 32 * j];

    float lg[E_NUM];
#pragma unroll
    for (int e = 0; e < E_NUM; e++) {
        float acc = 0.f;
#pragma unroll
        for (int j = 0; j < 32; j++)
            acc = fmaf(xr[j], rws[e * D_DIM + lane + 32 * j], acc);
#pragma unroll
        for (int o = 16; o; o >>= 1) acc += __shfl_xor_sync(0xffffffffu, acc, o);
        lg[e] = acc;
    }

    if (lane == 0) {
        int i0 = 0; float v0 = lg[0];
#pragma unroll
        for (int e = 1; e < E_NUM; e++) if (lg[e] > v0) { v0 = lg[e]; i0 = e; }
        int i1 = -1; float v1 = -3.0e38f;
#pragma unroll
        for (int e = 0; e < E_NUM; e++)
            if (e != i0 && lg[e] > v1) { v1 = lg[e]; i1 = e; }
        float r = expf(v1 - v0);
        float s = 1.f + r;
        g_top_i[2 * wid] = i0;  g_top_i[2 * wid + 1] = i1;
        g_top_w[2 * wid] = 1.f / s;  g_top_w[2 * wid + 1] = r / s;
        if (mask[wid] != 0) {
            atomicAdd(&g_counts[i0], 1);
            atomicAdd(&g_counts[i1], 1);
        }
    }
}

__global__ void offsets_kernel() {
    if (threadIdx.x == 0) {
        int s = 0;
        for (int e = 0; e < E_NUM; e++) { g_offsets[e] = s; s += g_counts[e]; }
    }
}

__global__ void scatter_kernel(const int* __restrict__ mask) {
    int t = blockIdx.x * blockDim.x + threadIdx.x;
    if (t >= T_TOK || mask[t] == 0) return;
#pragma unroll
    for (int k = 0; k < 2; k++) {
        int e   = g_top_i[2 * t + k];
        int pos = atomicAdd(&g_cursor[e], 1);
        int idx = g_offsets[e] + pos;
        g_rows_token[idx] = t;
        g_rows_w[idx]     = g_top_w[2 * t + k];
    }
}

// ---------------- x -> fp16 ---------------------------------------------------
__global__ void convert_x(const float* __restrict__ x) {
    size_t i = ((size_t)blockIdx.x * blockDim.x + threadIdx.x) * 8;
    if (i >= (size_t)T_TOK * D_DIM) return;
    float4 a = *(const float4*)(x + i);
    float4 b = *(const float4*)(x + i + 4);
    __half h[8] = {__float2half(a.x), __float2half(a.y),
                   __float2half(a.z), __float2half(a.w),
                   __float2half(b.x), __float2half(b.y),
                   __float2half(b.z), __float2half(b.w)};
    *(uint4*)(g_x16 + i) = *(uint4*)h;
}

// ---------------- weight transpose to fp16 -----------------------------------
// in: [E][K][N] fp32 -> out: [E][N][K] fp16
__device__ __forceinline__ void tq_body(const float* __restrict__ in,
                                        __half* __restrict__ o16,
                                        int K, int N) {
    __shared__ float t[32][33];
    int k0 = blockIdx.y * 32, n0 = blockIdx.x * 32;
    size_t eb = (size_t)blockIdx.z * K * N;
    const float* p = in + eb + (size_t)k0 * N + n0;
#pragma unroll
    for (int i = 0; i < 4; i++)
        t[threadIdx.y + 8 * i][threadIdx.x] =
            p[(size_t)(threadIdx.y + 8 * i) * N + threadIdx.x];
    __syncthreads();
#pragma unroll
    for (int i = 0; i < 4; i++) {
        int n = n0 + threadIdx.y + 8 * i;
        float v = t[threadIdx.x][threadIdx.y + 8 * i];
        o16[eb + (size_t)n * K + k0 + threadIdx.x] = __float2half(v);
    }
}
__global__ void convert_w1(const float* __restrict__ w) {
    tq_body(w, g_w1t, D_DIM, F_DIM);
}
__global__ void convert_w2(const float* __restrict__ w) {
    tq_body(w, g_w2t, F_DIM, D_DIM);
}

// ---------------- grouped GEMM: plain fp16 HMMA, fp32 accum ------------------
// G1: H[r,:]  = relu(x[tok(r),:] @ w1[e] + b1[e])      K=1024, N=2048
// G2: out[t,:] += w(r) * (H[r,:] @ w2[e] + b2[e])      K=2048, N=1024
template <bool G1>
__global__ __launch_bounds__(256, 1)
void gemm_kernel(const float* __restrict__ bias, float* __restrict__ outp) {
    constexpr int KTOT = G1 ? D_DIM : F_DIM;
    constexpr int NTOT = G1 ? F_DIM : D_DIM;
    constexpr int NCH  = KTOT / BK;

    extern __shared__ __align__(1024) char smem[];
    const uint32_t sb = smem_u32(smem);
    int* tok_s = (int*)smem;                 // [0,512)
    const int BUF0 = 1024;                   // 3 stages x (A 16K | B 16K)

    int e    = blockIdx.z;
    int n_e  = g_counts[e];
    int row0 = blockIdx.y * BM;
    if (row0 >= n_e) return;
    int base = g_offsets[e];
    int n0   = blockIdx.x * BN;

    int tid = threadIdx.x, w = tid >> 5, lane = tid & 31;
    int wm = w >> 2, wn = w & 3;             // 2x4 warps, warp tile 64m x 32n

    if (G1 && tid < BM) {
        int r = row0 + tid;
        tok_s[tid] = (r < n_e) ? g_rows_token[base + r] : -1;
    }
    __syncthreads();

    const __half* Bw = G1 ? (g_w1t + ((size_t)e * F_DIM + n0) * D_DIM)
                          : (g_w2t + ((size_t)e * D_DIM + n0) * F_DIM);

    // load geometry: 2 threads per row; each thread 4x16B per matrix
    int lrow = tid >> 1, lhalf = tid & 1;

    const __half* aP;
    int azf = 16;
    if constexpr (G1) {
        int tk = tok_s[lrow];
        if (tk >= 0) {
            aP = g_x16 + (size_t)tk * D_DIM;
        } else {
            aP = g_x16; azf = 0;             // zero-fill
        }
    } else {
        int rr = row0 + lrow; if (rr >= n_e) rr = n_e - 1;
        aP = g_H16 + (size_t)(base + rr) * F_DIM;
    }
    const __half* bP = Bw + (size_t)lrow * KTOT;

    auto issue = [&](int c) {
        int stage = c % 3;
        int k0 = c * BK;
        uint32_t dA = sb + BUF0 + stage * STAGE_BYTES;
        uint32_t dB = dA + 16384;
#pragma unroll
        for (int s = 0; s < 4; s++) {
            int cb = (lhalf * 4 + s) * 16;               // byte within 128B row
            uint32_t doff = SWZ128(lrow * 128 + cb);
            cp16(dA + doff, (const char*)(aP + k0) + cb, azf);
            cp16(dB + doff, (const char*)(bP + k0) + cb, 16);
        }
        cp_commit();
    };

    float acc[4][4][4];
#pragma unroll
    for (int i = 0; i < 4; i++)
#pragma unroll
        for (int j = 0; j < 4; j++)
#pragma unroll
            for (int q = 0; q < 4; q++) acc[i][j][q] = 0.f;

    // ldmatrix lane-address components (validated R3-R5 geometry)
    int aR = (lane & 7) + ((lane >> 3) & 1) * 8;
    int aC = lane >> 4;
    int bRw = (lane & 7) + (lane >> 4) * 8;
    int bC = (lane >> 3) & 1;

    issue(0);
    issue(1);

    for (int c = 0; c < NCH; c++) {
        cp_wait1();
        __syncthreads();
        if (c + 2 < NCH) issue(c + 2);
        else cp_commit();                    // keep group accounting uniform

        uint32_t bufA = sb + BUF0 + (c % 3) * STAGE_BYTES;
        uint32_t bufB = bufA + 16384;
#pragma unroll
        for (int ks = 0; ks < 4; ks++) {
            uint32_t fB[4][2], tmp[4];
#pragma unroll
            for (int pp = 0; pp < 2; pp++) {
                int off = (wn * 32 + pp * 16 + bRw) * 128 + (ks * 2 + bC) * 16;
                ldsm4(tmp, bufB + SWZ128(off));
                fB[pp * 2][0] = tmp[0]; fB[pp * 2][1] = tmp[1];
                fB[pp * 2 + 1][0] = tmp[2]; fB[pp * 2 + 1][1] = tmp[3];
            }
            uint32_t fA[4][4];
#pragma unroll
            for (int mf = 0; mf < 4; mf++) {
                int off = (wm * 64 + mf * 16 + aR) * 128 + (ks * 2 + aC) * 16;
                ldsm4(fA[mf], bufA + SWZ128(off));
            }
#pragma unroll
            for (int mf = 0; mf < 4; mf++)
#pragma unroll
                for (int nf = 0; nf < 4; nf++)
                    hmma(acc[mf][nf], fA[mf], fB[nf]);
        }
        __syncthreads();
    }

    // ---------------- epilogue ----------------
    int g = lane >> 2, t4 = lane & 3;
    float bia[4][2];
#pragma unroll
    for (int nf = 0; nf < 4; nf++) {
#pragma unroll
        for (int j = 0; j < 2; j++)
            bia[nf][j] = bias[(size_t)e * NTOT + n0 + wn * 32 + nf * 8 + t4 * 2 + j];
    }

#pragma unroll
    for (int mf = 0; mf < 4; mf++) {
#pragma unroll
        for (int half = 0; half < 2; half++) {
            int r = row0 + wm * 64 + mf * 16 + g + half * 8;
            if (r >= n_e) continue;
            if constexpr (G1) {
                size_t ro = (size_t)(base + r) * F_DIM;
#pragma unroll
                for (int nf = 0; nf < 4; nf++) {
                    int col = n0 + wn * 32 + nf * 8 + t4 * 2;
                    float v0 = fmaxf(acc[mf][nf][2 * half + 0] + bia[nf][0], 0.f);
                    float v1 = fmaxf(acc[mf][nf][2 * half + 1] + bia[nf][1], 0.f);
                    *(__half2*)(g_H16 + ro + col) =
                        __halves2half2(__float2half(v0), __float2half(v1));
                }
            } else {
                int   t  = g_rows_token[base + r];
                float ww = g_rows_w[base + r];
                float* op = outp + (size_t)t * D_DIM;
#pragma unroll
                for (int nf = 0; nf < 4; nf++) {
                    int col = n0 + wn * 32 + nf * 8 + t4 * 2;
                    atomicAdd(op + col,
                              ww * (acc[mf][nf][2 * half + 0] + bia[nf][0]));
                    atomicAdd(op + col + 1,
                              ww * (acc[mf][nf][2 * half + 1] + bia[nf][1]));
                }
            }
        }
    }
}

// ---------------- launch -----------------------------------------------------
extern "C" void kernel_launch(void* const* d_in, const int* in_sizes, int n_in,
                              void* d_out, int out_size) {
    const float* x    = (const float*)d_in[0];
    const int*   mask = (const int*)d_in[1];
    const float* rw   = (const float*)d_in[2];
    const float* w1   = (const float*)d_in[3];
    const float* b1   = (const float*)d_in[4];
    const float* w2   = (const float*)d_in[5];
    const float* b2   = (const float*)d_in[6];
    float*       out  = (float*)d_out;

    cudaFuncSetAttribute(gemm_kernel<true>,
                         cudaFuncAttributeMaxDynamicSharedMemorySize, SMEM_SZ);
    cudaFuncSetAttribute(gemm_kernel<false>,
                         cudaFuncAttributeMaxDynamicSharedMemorySize, SMEM_SZ);

    cudaMemsetAsync(out, 0, (size_t)T_TOK * D_DIM * sizeof(float));
    init_kernel<<<1, 32>>>();

    convert_x<<<(T_TOK * D_DIM / 8 + 255) / 256, 256>>>(x);
    convert_w1<<<dim3(F_DIM / 32, D_DIM / 32, E_NUM), dim3(32, 8)>>>(w1);
    convert_w2<<<dim3(D_DIM / 32, F_DIM / 32, E_NUM), dim3(32, 8)>>>(w2);

    router_kernel<<<T_TOK / 8, 256>>>(x, mask, rw);
    offsets_kernel<<<1, 32>>>();
    scatter_kernel<<<(T_TOK + 255) / 256, 256>>>(mask);

    dim3 g1(F_DIM / BN, RMAX / BM, E_NUM);
    gemm_kernel<true><<<g1, 256, SMEM_SZ>>>(b1, out);
    dim3 g2(D_DIM / BN, RMAX / BM, E_NUM);
    gemm_kernel<false><<<g2, 256, SMEM_SZ>>>(b2, out);
}

// round 8
// speedup vs baseline: 7.1652x; 1.2018x over previous
#include <cuda_runtime.h>
#include <cuda_fp16.h>
#include <cstdint>

// Problem constants (B=4, S=2048, D=1024, E=8, F=2048, top_k=2)
#define T_TOK 8192
#define D_DIM 1024
#define E_NUM 8
#define F_DIM 2048
#define RMAX  (2 * T_TOK)

#define BM 128
#define BN 128
#define BK 64                         // 64 fp16 k-values = 128B rows
#define STAGE_BYTES (2 * 16384)       // A | B, 16KB each
#define SMEM_SZ (1024 + 2 * STAGE_BYTES)   // 2-stage -> 65KB, 2 CTAs/SM

// ---------------- device scratch (no allocation allowed) --------------------
__device__ __half g_x16[(size_t)T_TOK * D_DIM];                // x fp16
__device__ __half g_H16[(size_t)RMAX * F_DIM];                 // H fp16
__device__ float  g_Y[(size_t)RMAX * D_DIM];                   // expert outputs
__device__ __half g_w1t[(size_t)E_NUM * F_DIM * D_DIM];        // [E][F][D] fp16
__device__ __half g_w2t[(size_t)E_NUM * D_DIM * F_DIM];        // [E][D][F] fp16
__device__ int   g_rows_token[RMAX];
__device__ int   g_tok2row[2 * T_TOK];
__device__ int   g_top_i[2 * T_TOK];
__device__ float g_top_w[2 * T_TOK];
__device__ int   g_counts[E_NUM];
__device__ int   g_offsets[E_NUM];
__device__ int   g_cursor[E_NUM];

// ---------------- helpers ----------------------------------------------------
__device__ __forceinline__ uint32_t smem_u32(const void* p) {
    uint32_t a;
    asm("{ .reg .u64 t; cvta.to.shared.u64 t, %1; cvt.u32.u64 %0, t; }"
        : "=r"(a) : "l"(p));
    return a;
}
// standard 128B-row swizzle (Swizzle<3,4,3>): 16B-col bits[6:4] ^= row bits[9:7]
#define SWZ128(o) ((o) ^ (((o) >> 3) & 0x70))

__device__ __forceinline__ void ldsm4(uint32_t* r, uint32_t addr) {
    asm volatile("ldmatrix.sync.aligned.m8n8.x4.shared.b16 {%0,%1,%2,%3}, [%4];"
                 : "=r"(r[0]), "=r"(r[1]), "=r"(r[2]), "=r"(r[3]) : "r"(addr));
}
__device__ __forceinline__ void hmma(float* c, const uint32_t* a,
                                     const uint32_t* b) {
    asm volatile(
        "mma.sync.aligned.m16n8k16.row.col.f32.f16.f16.f32 "
        "{%0,%1,%2,%3}, {%4,%5,%6,%7}, {%8,%9}, {%0,%1,%2,%3};"
        : "+f"(c[0]), "+f"(c[1]), "+f"(c[2]), "+f"(c[3])
        : "r"(a[0]), "r"(a[1]), "r"(a[2]), "r"(a[3]), "r"(b[0]), "r"(b[1]));
}
__device__ __forceinline__ void cp16(uint32_t dst, const void* src, int nbytes) {
    asm volatile("cp.async.cg.shared.global [%0], [%1], 16, %2;"
                 :: "r"(dst), "l"(src), "r"(nbytes) : "memory");
}
__device__ __forceinline__ void cp_commit() {
    asm volatile("cp.async.commit_group;" ::: "memory");
}
__device__ __forceinline__ void cp_wait1() {
    asm volatile("cp.async.wait_group 1;" ::: "memory");
}

// ---------------- init / router / scatter ------------------------------------
__global__ void init_kernel() {
    int i = threadIdx.x;
    if (i < E_NUM) { g_counts[i] = 0; g_cursor[i] = 0; }
}

__global__ void router_kernel(const float* __restrict__ x,
                              const int* __restrict__ mask,
                              const float* __restrict__ rw) {
    __shared__ float rws[E_NUM * D_DIM];
    for (int i = threadIdx.x; i < E_NUM * D_DIM; i += blockDim.x) {
        int d = i >> 3, e = i & 7;
        rws[e * D_DIM + d] = rw[i];
    }
    __syncthreads();

    int wid  = blockIdx.x * (blockDim.x >> 5) + (threadIdx.x >> 5);
    int lane = threadIdx.x & 31;
    if (wid >= T_TOK) return;

    const float* xp = x + (size_t)wid * D_DIM;
    float xr[32];
#pragma unroll
    for (int j = 0; j < 32; j++) xr[j] = xp[lane + 32 * j];

    float lg[E_NUM];
#pragma unroll
    for (int e = 0; e < E_NUM; e++) {
        float acc = 0.f;
#pragma unroll
        for (int j = 0; j < 32; j++)
            acc = fmaf(xr[j], rws[e * D_DIM + lane + 32 * j], acc);
#pragma unroll
        for (int o = 16; o; o >>= 1) acc += __shfl_xor_sync(0xffffffffu, acc, o);
        lg[e] = acc;
    }

    if (lane == 0) {
        int i0 = 0; float v0 = lg[0];
#pragma unroll
        for (int e = 1; e < E_NUM; e++) if (lg[e] > v0) { v0 = lg[e]; i0 = e; }
        int i1 = -1; float v1 = -3.0e38f;
#pragma unroll
        for (int e = 0; e < E_NUM; e++)
            if (e != i0 && lg[e] > v1) { v1 = lg[e]; i1 = e; }
        float r = expf(v1 - v0);
        float s = 1.f + r;
        g_top_i[2 * wid] = i0;  g_top_i[2 * wid + 1] = i1;
        g_top_w[2 * wid] = 1.f / s;  g_top_w[2 * wid + 1] = r / s;
        if (mask[wid] != 0) {
            atomicAdd(&g_counts[i0], 1);
            atomicAdd(&g_counts[i1], 1);
        }
    }
}

__global__ void offsets_kernel() {
    if (threadIdx.x == 0) {
        int s = 0;
        for (int e = 0; e < E_NUM; e++) { g_offsets[e] = s; s += g_counts[e]; }
    }
}

__global__ void scatter_kernel(const int* __restrict__ mask) {
    int t = blockIdx.x * blockDim.x + threadIdx.x;
    if (t >= T_TOK || mask[t] == 0) return;
#pragma unroll
    for (int k = 0; k < 2; k++) {
        int e   = g_top_i[2 * t + k];
        int pos = atomicAdd(&g_cursor[e], 1);
        int idx = g_offsets[e] + pos;
        g_rows_token[idx]  = t;
        g_tok2row[2 * t + k] = idx;
    }
}

// ---------------- x -> fp16 ---------------------------------------------------
__global__ void convert_x(const float* __restrict__ x) {
    size_t i = ((size_t)blockIdx.x * blockDim.x + threadIdx.x) * 8;
    if (i >= (size_t)T_TOK * D_DIM) return;
    float4 a = *(const float4*)(x + i);
    float4 b = *(const float4*)(x + i + 4);
    __half h[8] = {__float2half(a.x), __float2half(a.y),
                   __float2half(a.z), __float2half(a.w),
                   __float2half(b.x), __float2half(b.y),
                   __float2half(b.z), __float2half(b.w)};
    *(uint4*)(g_x16 + i) = *(uint4*)h;
}

// ---------------- weight transpose to fp16 -----------------------------------
// in: [E][K][N] fp32 -> out: [E][N][K] fp16
__device__ __forceinline__ void tq_body(const float* __restrict__ in,
                                        __half* __restrict__ o16,
                                        int K, int N) {
    __shared__ float t[32][33];
    int k0 = blockIdx.y * 32, n0 = blockIdx.x * 32;
    size_t eb = (size_t)blockIdx.z * K * N;
    const float* p = in + eb + (size_t)k0 * N + n0;
#pragma unroll
    for (int i = 0; i < 4; i++)
        t[threadIdx.y + 8 * i][threadIdx.x] =
            p[(size_t)(threadIdx.y + 8 * i) * N + threadIdx.x];
    __syncthreads();
#pragma unroll
    for (int i = 0; i < 4; i++) {
        int n = n0 + threadIdx.y + 8 * i;
        float v = t[threadIdx.x][threadIdx.y + 8 * i];
        o16[eb + (size_t)n * K + k0 + threadIdx.x] = __float2half(v);
    }
}
__global__ void convert_w1(const float* __restrict__ w) {
    tq_body(w, g_w1t, D_DIM, F_DIM);
}
__global__ void convert_w2(const float* __restrict__ w) {
    tq_body(w, g_w2t, F_DIM, D_DIM);
}

// ---------------- grouped GEMM: plain fp16 HMMA, fp32 accum ------------------
// G1: H[r,:] = relu(x[tok(r),:] @ w1[e] + b1[e])      K=1024, N=2048
// G2: Y[r,:] = H[r,:] @ w2[e] + b2[e]                 K=2048, N=1024
template <bool G1>
__global__ __launch_bounds__(256, 2)
void gemm_kernel(const float* __restrict__ bias) {
    constexpr int KTOT = G1 ? D_DIM : F_DIM;
    constexpr int NTOT = G1 ? F_DIM : D_DIM;
    constexpr int NCH  = KTOT / BK;

    extern __shared__ __align__(1024) char smem[];
    const uint32_t sb = smem_u32(smem);
    int* tok_s = (int*)smem;                 // [0,512)
    const int BUF0 = 1024;                   // 2 stages x (A 16K | B 16K)

    int e    = blockIdx.z;
    int n_e  = g_counts[e];
    int row0 = blockIdx.y * BM;
    if (row0 >= n_e) return;
    int base = g_offsets[e];
    int n0   = blockIdx.x * BN;

    int tid = threadIdx.x, w = tid >> 5, lane = tid & 31;
    int wm = w >> 2, wn = w & 3;             // 2x4 warps, warp tile 64m x 32n

    if (G1 && tid < BM) {
        int r = row0 + tid;
        tok_s[tid] = (r < n_e) ? g_rows_token[base + r] : -1;
    }
    __syncthreads();

    const __half* Bw = G1 ? (g_w1t + ((size_t)e * F_DIM + n0) * D_DIM)
                          : (g_w2t + ((size_t)e * D_DIM + n0) * F_DIM);

    // load geometry: 2 threads per row; each thread 4x16B per matrix
    int lrow = tid >> 1, lhalf = tid & 1;

    const __half* aP;
    int azf = 16;
    if constexpr (G1) {
        int tk = tok_s[lrow];
        if (tk >= 0) {
            aP = g_x16 + (size_t)tk * D_DIM;
        } else {
            aP = g_x16; azf = 0;             // zero-fill
        }
    } else {
        int rr = row0 + lrow; if (rr >= n_e) rr = n_e - 1;
        aP = g_H16 + (size_t)(base + rr) * F_DIM;
    }
    const __half* bP = Bw + (size_t)lrow * KTOT;

    auto issue = [&](int c) {
        int k0 = c * BK;
        uint32_t dA = sb + BUF0 + (c & 1) * STAGE_BYTES;
        uint32_t dB = dA + 16384;
#pragma unroll
        for (int s = 0; s < 4; s++) {
            int cb = (lhalf * 4 + s) * 16;               // byte within 128B row
            uint32_t doff = SWZ128(lrow * 128 + cb);
            cp16(dA + doff, (const char*)(aP + k0) + cb, azf);
            cp16(dB + doff, (const char*)(bP + k0) + cb, 16);
        }
        cp_commit();
    };

    float acc[4][4][4];
#pragma unroll
    for (int i = 0; i < 4; i++)
#pragma unroll
        for (int j = 0; j < 4; j++)
#pragma unroll
            for (int q = 0; q < 4; q++) acc[i][j][q] = 0.f;

    // ldmatrix lane-address components (validated R3-R6 geometry)
    int aR = (lane & 7) + ((lane >> 3) & 1) * 8;
    int aC = lane >> 4;
    int bRw = (lane & 7) + (lane >> 4) * 8;
    int bC = (lane >> 3) & 1;

    issue(0);
    issue(1);

    for (int c = 0; c < NCH; c++) {
        cp_wait1();
        __syncthreads();

        uint32_t bufA = sb + BUF0 + (c & 1) * STAGE_BYTES;
        uint32_t bufB = bufA + 16384;
#pragma unroll
        for (int ks = 0; ks < 4; ks++) {
            uint32_t fB[4][2], tmp[4];
#pragma unroll
            for (int pp = 0; pp < 2; pp++) {
                int off = (wn * 32 + pp * 16 + bRw) * 128 + (ks * 2 + bC) * 16;
                ldsm4(tmp, bufB + SWZ128(off));
                fB[pp * 2][0] = tmp[0]; fB[pp * 2][1] = tmp[1];
                fB[pp * 2 + 1][0] = tmp[2]; fB[pp * 2 + 1][1] = tmp[3];
            }
            uint32_t fA[4][4];
#pragma unroll
            for (int mf = 0; mf < 4; mf++) {
                int off = (wm * 64 + mf * 16 + aR) * 128 + (ks * 2 + aC) * 16;
                ldsm4(fA[mf], bufA + SWZ128(off));
            }
#pragma unroll
            for (int mf = 0; mf < 4; mf++)
#pragma unroll
                for (int nf = 0; nf < 4; nf++)
                    hmma(acc[mf][nf], fA[mf], fB[nf]);
        }
        __syncthreads();
        if (c + 2 < NCH) issue(c + 2);
        else cp_commit();                    // keep group accounting uniform
    }

    // ---------------- epilogue ----------------
    int g = lane >> 2, t4 = lane & 3;
    float bia[4][2];
#pragma unroll
    for (int nf = 0; nf < 4; nf++) {
#pragma unroll
        for (int j = 0; j < 2; j++)
            bia[nf][j] = bias[(size_t)e * NTOT + n0 + wn * 32 + nf * 8 + t4 * 2 + j];
    }

#pragma unroll
    for (int mf = 0; mf < 4; mf++) {
#pragma unroll
        for (int half = 0; half < 2; half++) {
            int r = row0 + wm * 64 + mf * 16 + g + half * 8;
            if (r >= n_e) continue;
            if constexpr (G1) {
                size_t ro = (size_t)(base + r) * F_DIM;
#pragma unroll
                for (int nf = 0; nf < 4; nf++) {
                    int col = n0 + wn * 32 + nf * 8 + t4 * 2;
                    float v0 = fmaxf(acc[mf][nf][2 * half + 0] + bia[nf][0], 0.f);
                    float v1 = fmaxf(acc[mf][nf][2 * half + 1] + bia[nf][1], 0.f);
                    *(__half2*)(g_H16 + ro + col) =
                        __halves2half2(__float2half(v0), __float2half(v1));
                }
            } else {
                size_t ro = (size_t)(base + r) * D_DIM;
#pragma unroll
                for (int nf = 0; nf < 4; nf++) {
                    int col = n0 + wn * 32 + nf * 8 + t4 * 2;
                    float2 v = make_float2(acc[mf][nf][2 * half + 0] + bia[nf][0],
                                           acc[mf][nf][2 * half + 1] + bia[nf][1]);
                    *(float2*)(g_Y + ro + col) = v;
                }
            }
        }
    }
}

// ---------------- combine: out[t] = w0*Y[row0] + w1*Y[row1] ------------------
__global__ void combine_kernel(const int* __restrict__ mask,
                               float* __restrict__ out) {
    int t  = blockIdx.x;
    int c4 = threadIdx.x * 4;
    float4 o = make_float4(0.f, 0.f, 0.f, 0.f);
    if (mask[t] != 0) {
        int   r0 = g_tok2row[2 * t],     r1 = g_tok2row[2 * t + 1];
        float w0 = g_top_w[2 * t],       w1 = g_top_w[2 * t + 1];
        float4 y0 = *(const float4*)(g_Y + (size_t)r0 * D_DIM + c4);
        float4 y1 = *(const float4*)(g_Y + (size_t)r1 * D_DIM + c4);
        o.x = w0 * y0.x + w1 * y1.x;
        o.y = w0 * y0.y + w1 * y1.y;
        o.z = w0 * y0.z + w1 * y1.z;
        o.w = w0 * y0.w + w1 * y1.w;
    }
    *(float4*)(out + (size_t)t * D_DIM + c4) = o;
}

// ---------------- launch -----------------------------------------------------
extern "C" void kernel_launch(void* const* d_in, const int* in_sizes, int n_in,
                              void* d_out, int out_size) {
    const float* x    = (const float*)d_in[0];
    const int*   mask = (const int*)d_in[1];
    const float* rw   = (const float*)d_in[2];
    const float* w1   = (const float*)d_in[3];
    const float* b1   = (const float*)d_in[4];
    const float* w2   = (const float*)d_in[5];
    const float* b2   = (const float*)d_in[6];
    float*       out  = (float*)d_out;

    cudaFuncSetAttribute(gemm_kernel<true>,
                         cudaFuncAttributeMaxDynamicSharedMemorySize, SMEM_SZ);
    cudaFuncSetAttribute(gemm_kernel<false>,
                         cudaFuncAttributeMaxDynamicSharedMemorySize, SMEM_SZ);

    init_kernel<<<1, 32>>>();

    convert_x<<<(T_TOK * D_DIM / 8 + 255) / 256, 256>>>(x);
    convert_w1<<<dim3(F_DIM / 32, D_DIM / 32, E_NUM), dim3(32, 8)>>>(w1);
    convert_w2<<<dim3(D_DIM / 32, F_DIM / 32, E_NUM), dim3(32, 8)>>>(w2);

    router_kernel<<<T_TOK / 8, 256>>>(x, mask, rw);
    offsets_kernel<<<1, 32>>>();
    scatter_kernel<<<(T_TOK + 255) / 256, 256>>>(mask);

    dim3 g1(F_DIM / BN, RMAX / BM, E_NUM);
    gemm_kernel<true><<<g1, 256, SMEM_SZ>>>(b1);
    dim3 g2(D_DIM / BN, RMAX / BM, E_NUM);
    gemm_kernel<false><<<g2, 256, SMEM_SZ>>>(b2);

    combine_kernel<<<T_TOK, 256>>>(mask, out);
}